// round 5
// baseline (speedup 1.0000x reference)
#include <cuda_runtime.h>
#include <cuda_bf16.h>
#include <math.h>

// Problem dims
#define Bv 128
#define Lv 512
#define Dv 512
#define Ev 64
#define Hv 512
#define Vv 17

#define FULLMASK 0xffffffffu

// Output layout (float32 concat of the 4 reference outputs)
#define OFF_LOGITS 0
#define OFF_PREDS  (Bv*Lv*Vv)                 // 1114112
#define OFF_PROBS  (OFF_PREDS + Bv*Lv)        // 1179648
#define OFF_EMB    (OFF_PROBS + Bv*Lv*Vv)     // 2293760

// Scratch: pre[b, t, h] (128 MB) + readiness flags per (b, t-chunk)
__device__ float g_pre[(size_t)Bv * Lv * Hv];
__device__ int   g_flag[Bv * 4];

// ---------------------------------------------------------------------------
__global__ void init_kernel() { g_flag[threadIdx.x] = 0; }

// ---------------------------------------------------------------------------
// fast warp argmax over lanes [0, Vv): monotone-uint transform + redux.max +
// ballot + ffs.  Uniform across the warp; first-max tie-break (jnp.argmax).
// ---------------------------------------------------------------------------
__device__ __forceinline__ int argmax17(float v, int lane)
{
    unsigned u = __float_as_uint(v);
    u = (u & 0x80000000u) ? ~u : (u | 0x80000000u);
    if (lane >= Vv) u = 0u;
    unsigned mx = __reduce_max_sync(FULLMASK, u);
    unsigned msk = __ballot_sync(FULLMASK, u == mx);
    return __ffs(msk) - 1;
}

// ---------------------------------------------------------------------------
// Fused producer-consumer kernel.
//   blockIdx.x <  128 : scan chain for batch b = blockIdx.x (consumer)
//   blockIdx.x >= 128 : one 128x128 GEMM tile of pre (producer),
//                       ordered (t-chunk, b, n-tile) so early t lands first.
// ---------------------------------------------------------------------------
__global__ __launch_bounds__(544, 2) void fused_kernel(
    const float* __restrict__ A,           // inputs [B, L, D]
    const float* __restrict__ emb_table,   // [V, E]
    const float* __restrict__ W1,          // [H, D+E]
    const float* __restrict__ b1,          // [H]
    const float* __restrict__ W2,          // [V, H]
    const float* __restrict__ b2,          // [V]
    float* __restrict__ out)
{
    __shared__ union {
        struct { float A[16][132]; float B[16][132]; } g;          // 16896 B
        struct { float M[Vv][Hv]; float H[Hv]; float L[20]; } s;   // 36944 B
    } u;

    const int tid  = threadIdx.x;
    const int lane = tid & 31;

    if (blockIdx.x >= Bv) {
        // ------------------------- GEMM producer role -------------------------
        const int tile = blockIdx.x - Bv;          // 0..2047
        const int tc   = tile >> 9;                // t-chunk 0..3
        const int rem  = tile & 511;
        const int b    = rem >> 2;                 // batch 0..127
        const int nt   = rem & 3;                  // n-tile 0..3
        const int bm   = b * Lv + tc * 128;        // row block in [B*L]
        const int bn   = nt * 128;

        const bool act = (tid < 512);
        const int tx = tid & 31;                   // N: 4 cols each
        const int ty = (tid >> 5) & 15;            // M: 8 rows each
        const int r  = tid >> 2;                   // staging row 0..127
        const int c4 = (tid & 3) * 4;              // staging col group

        const float* aP = A  + (size_t)(bm + r) * Dv + c4;
        const float* wP = W1 + (size_t)(bn + r) * (Dv + Ev) + c4;

        float acc[8][4];
#pragma unroll
        for (int i = 0; i < 8; i++)
#pragma unroll
            for (int j = 0; j < 4; j++) acc[i][j] = 0.f;

        for (int k0 = 0; k0 < Dv; k0 += 16) {
            if (act) {
                float4 va = *reinterpret_cast<const float4*>(aP + k0);
                float4 vb = *reinterpret_cast<const float4*>(wP + k0);
                u.g.A[c4 + 0][r] = va.x; u.g.A[c4 + 1][r] = va.y;
                u.g.A[c4 + 2][r] = va.z; u.g.A[c4 + 3][r] = va.w;
                u.g.B[c4 + 0][r] = vb.x; u.g.B[c4 + 1][r] = vb.y;
                u.g.B[c4 + 2][r] = vb.z; u.g.B[c4 + 3][r] = vb.w;
            }
            __syncthreads();
            if (act) {
#pragma unroll
                for (int k = 0; k < 16; k++) {
                    float4 av0 = *reinterpret_cast<const float4*>(&u.g.A[k][ty * 8]);
                    float4 av1 = *reinterpret_cast<const float4*>(&u.g.A[k][ty * 8 + 4]);
                    float4 bv  = *reinterpret_cast<const float4*>(&u.g.B[k][tx * 4]);
                    float a[8] = {av0.x, av0.y, av0.z, av0.w,
                                  av1.x, av1.y, av1.z, av1.w};
                    float bb[4] = {bv.x, bv.y, bv.z, bv.w};
#pragma unroll
                    for (int i = 0; i < 8; i++)
#pragma unroll
                        for (int j = 0; j < 4; j++) acc[i][j] += a[i] * bb[j];
                }
            }
            __syncthreads();
        }

        if (act) {
            float bb[4];
#pragma unroll
            for (int j = 0; j < 4; j++) bb[j] = b1[bn + tx * 4 + j];
#pragma unroll
            for (int i = 0; i < 8; i++) {
                size_t row = (size_t)(bm + ty * 8 + i);
                float4 v;
                v.x = acc[i][0] + bb[0];
                v.y = acc[i][1] + bb[1];
                v.z = acc[i][2] + bb[2];
                v.w = acc[i][3] + bb[3];
                *reinterpret_cast<float4*>(&g_pre[row * Hv + bn + tx * 4]) = v;
            }
        }
        __threadfence();        // make tile visible GPU-wide
        __syncthreads();        // all threads' stores done before flag
        if (tid == 0) atomicAdd(&g_flag[b * 4 + tc], 1);
        return;
    }

    // --------------------------- scan consumer role ---------------------------
    const int b = blockIdx.x;
    const int w = tid >> 5;

    // Precompute M[v][h] = sum_e table[v][e] * W1[h][D+e]; row 0 zero (padding)
    for (int idx = tid; idx < Vv * Hv; idx += 544) {
        int v = idx / Hv, h = idx - v * Hv;
        float acc = 0.f;
        if (v != 0) {
            const float* er = emb_table + v * Ev;
            const float* wr = W1 + (size_t)h * (Dv + Ev) + Dv;
#pragma unroll 8
            for (int e = 0; e < Ev; e++) acc += er[e] * wr[e];
        }
        u.s.M[v][h] = acc;
    }

    // W2 rows in registers: warp w owns logit w (w < 17 always)
    float w2r[16];
#pragma unroll
    for (int k = 0; k < 16; k++) w2r[k] = W2[(size_t)w * Hv + k * 32 + lane];
    const float bias2 = b2[w];
    __syncthreads();

    float* outL = out + OFF_LOGITS;
    float* outP = out + OFF_PREDS;
    const float* preB = g_pre + (size_t)b * Lv * Hv;

    for (int tc = 0; tc < 4; tc++) {
        // wait for this chunk of pre to be produced (4 n-tiles)
        if (tid == 0) {
            while (((volatile int*)g_flag)[b * 4 + tc] < 4) __nanosleep(128);
            __threadfence();
        }
        __syncthreads();

        const int tbase = tc * 128;
        float pcur = (tid < Hv) ? preB[(size_t)tbase * Hv + tid] : 0.f;

        for (int tt = 0; tt < 128; tt++) {
            const int t = tbase + tt;
            float pnxt = 0.f;
            if (tid < Hv && tt + 1 < 128)
                pnxt = preB[(size_t)(t + 1) * Hv + tid];

            // stage A: argmax of previous logits (every warp), then hidden
            int pred;
            if (t == 0) {
                pred = 0;   // PAD
            } else {
                pred = argmax17((lane < Vv) ? u.s.L[lane] : 0.f, lane);
                if (tid == 0) outP[(size_t)b * Lv + (t - 1)] = (float)pred;
            }
            if (tid < Hv) u.s.H[tid] = tanhf(pcur + u.s.M[pred][tid]);
            __syncthreads();

            // stage B: warp w computes logit[w]
            {
                float acc = 0.f;
#pragma unroll
                for (int k = 0; k < 16; k++) acc += u.s.H[k * 32 + lane] * w2r[k];
#pragma unroll
                for (int off = 16; off; off >>= 1)
                    acc += __shfl_xor_sync(FULLMASK, acc, off);
                if (lane == 0) {
                    float lg = acc + bias2;
                    u.s.L[w] = lg;
                    outL[((size_t)b * Lv + t) * Vv + w] = lg;
                }
            }
            __syncthreads();

            pcur = pnxt;
        }
    }

    // tail: argmax for the final timestep
    if (w == 0) {
        int pred = argmax17((lane < Vv) ? u.s.L[lane] : 0.f, lane);
        if (lane == 0) outP[(size_t)b * Lv + (Lv - 1)] = (float)pred;
    }
}

// ---------------------------------------------------------------------------
// Parallel post-pass — log-softmax from saved logits, preds_emb.
// ---------------------------------------------------------------------------
__global__ __launch_bounds__(256) void post_kernel(
    const float* __restrict__ emb_table,
    float* __restrict__ out)
{
    const float* outL = out + OFF_LOGITS;
    const float* outP = out + OFF_PREDS;
    float* outQ  = out + OFF_PROBS;
    float* outEb = out + OFF_EMB;

    const int lane = threadIdx.x & 31;
    const int warps_total = (gridDim.x * blockDim.x) >> 5;
    int gw = (blockIdx.x * blockDim.x + threadIdx.x) >> 5;

    for (int row = gw; row < Bv * Lv; row += warps_total) {
        float v = (lane < Vv) ? outL[(size_t)row * Vv + lane] : -1e30f;
        float m = v;
#pragma unroll
        for (int off = 16; off; off >>= 1)
            m = fmaxf(m, __shfl_xor_sync(FULLMASK, m, off));
        float e = (lane < Vv) ? expf(v - m) : 0.f;
        float s = e;
#pragma unroll
        for (int off = 16; off; off >>= 1)
            s += __shfl_xor_sync(FULLMASK, s, off);
        float lse = m + logf(s);
        if (lane < Vv) outQ[(size_t)row * Vv + lane] = v - lse;

        int pred = (int)outP[row];
        float e0 = (pred != 0) ? emb_table[pred * Ev + lane] : 0.f;
        float e1 = (pred != 0) ? emb_table[pred * Ev + 32 + lane] : 0.f;
        outEb[(size_t)row * Ev + lane]      = e0;
        outEb[(size_t)row * Ev + 32 + lane] = e1;
    }
}

// ---------------------------------------------------------------------------
extern "C" void kernel_launch(void* const* d_in, const int* in_sizes, int n_in,
                              void* d_out, int out_size)
{
    const float* inputs    = (const float*)d_in[0];  // [B, L, D]
    const float* emb_table = (const float*)d_in[1];  // [V, E]
    const float* W1        = (const float*)d_in[2];  // [H, D+E]
    const float* b1        = (const float*)d_in[3];  // [H]
    const float* W2        = (const float*)d_in[4];  // [V, H]
    const float* b2        = (const float*)d_in[5];  // [V]
    float* out = (float*)d_out;

    (void)in_sizes; (void)n_in; (void)out_size;

    init_kernel<<<1, Bv * 4>>>();

    // 128 scan CTAs + 2048 GEMM-tile CTAs in one launch
    fused_kernel<<<Bv + 2048, 544>>>(inputs, emb_table, W1, b1, W2, b2, out);

    post_kernel<<<256, 256>>>(emb_table, out);
}

// round 9
// speedup vs baseline: 2.1343x; 2.1343x over previous
#include <cuda_runtime.h>
#include <cuda_bf16.h>
#include <cstdint>
#include <math.h>

// Problem dims
#define Bv 128
#define Lv 512
#define Dv 512
#define Ev 64
#define Hv 512
#define Vv 17

#define FULLMASK 0xffffffffu

// Output layout (float32 concat of the 4 reference outputs)
#define OFF_LOGITS 0
#define OFF_PREDS  (Bv*Lv*Vv)                 // 1114112
#define OFF_PROBS  (OFF_PREDS + Bv*Lv)        // 1179648
#define OFF_EMB    (OFF_PROBS + Bv*Lv*Vv)     // 2293760

// Scratch: pre[b, t, h] = inputs[b,t,:] @ W1[:, :D]^T + b1   (128 MB)
__device__ float g_pre[(size_t)Bv * Lv * Hv];

// ---------------------------------------------------------------------------
__device__ __forceinline__ float tf32_rna(float x) {
    uint32_t u;
    asm("cvt.rna.tf32.f32 %0, %1;" : "=r"(u) : "f"(x));
    return __uint_as_float(u);
}

__device__ __forceinline__ void mma_tf32(
    float* d, const uint32_t* a, const uint32_t* b)
{
    asm volatile(
        "mma.sync.aligned.m16n8k8.row.col.f32.tf32.tf32.f32 "
        "{%0,%1,%2,%3}, {%4,%5,%6,%7}, {%8,%9}, {%0,%1,%2,%3};\n"
        : "+f"(d[0]), "+f"(d[1]), "+f"(d[2]), "+f"(d[3])
        : "r"(a[0]), "r"(a[1]), "r"(a[2]), "r"(a[3]),
          "r"(b[0]), "r"(b[1]));
}

// dynamic smem layout in floats: Ahi | Alo | Bhi | Blo, 4096 floats each (64KB)
#define F_AHI 0
#define F_ALO 4096
#define F_BHI 8192
#define F_BLO 12288
#define SM_TOT_BYTES (16384 * 4)

// ---------------------------------------------------------------------------
// Kernel 1: pre = A @ W1x^T + b1 via mma.sync tf32, 3-term precision split.
// 2048 CTAs x 256 threads, 128x128 tile, BK=32.
// Fragment-major smem layout so each fragment load is one LDS.128 / LDS.64:
//   A: [ks(4)][mf(8)][lane(32)][reg(4)]   (4096 floats)
//   B: [ks(4)][nf(16)][lane(32)][reg(2)]  (4096 floats)
// ---------------------------------------------------------------------------
__global__ __launch_bounds__(256) void gemm_mma_kernel(
    const float* __restrict__ A,      // [B*L, D]
    const float* __restrict__ W,      // [H, D+E]
    const float* __restrict__ bias)   // [H]
{
    extern __shared__ float sm[];

    const int tid  = threadIdx.x;
    const int w    = tid >> 5;
    const int lane = tid & 31;
    const int wm   = w >> 2;          // 0..1  (m offset 64)
    const int wn   = w & 3;           // 0..3  (n offset 32)

    const int bm = (blockIdx.x >> 2) * 128;   // row block in [B*L]
    const int bn = (blockIdx.x & 3) * 128;    // col block in [H]

    // staging mapping: thread t handles row = t>>1, k-cols cgrp..cgrp+15
    const int srow = tid >> 1;
    const int cgrp = (tid & 1) * 16;

    const float* aP = A + (size_t)(bm + srow) * Dv + cgrp;
    const float* wP = W + (size_t)(bn + srow) * (Dv + Ev) + cgrp;

    float acc[4][4][4];
#pragma unroll
    for (int i = 0; i < 4; i++)
#pragma unroll
        for (int j = 0; j < 4; j++)
#pragma unroll
            for (int r = 0; r < 4; r++) acc[i][j][r] = 0.f;

    // A-row scatter base pieces (row fixed per thread)
    const int a_mf  = srow >> 4;
    const int a_r16 = srow & 15;
    const int a_lb  = (a_r16 & 7) << 2;       // lane base (|= c&3)
    const int a_rb  = a_r16 >> 3;             // reg base  (+= 2*(c8>>2))
    // B-row scatter base pieces
    const int b_nf  = srow >> 3;
    const int b_lb  = (srow & 7) << 2;

    for (int ch = 0; ch < 16; ch++) {
        const int k0 = ch * 32;
        // ---- stage: load 16 A + 16 B floats, split, scatter to frag layout --
#pragma unroll
        for (int q = 0; q < 4; q++) {
            const int kc = cgrp + q * 4;          // chunk-local k col (mult of 4)
            const int ks = kc >> 3;
            const int c8 = kc & 7;
            float4 av = *reinterpret_cast<const float4*>(aP + k0 + q * 4);
            float4 bv = *reinterpret_cast<const float4*>(wP + k0 + q * 4);

            // A scatter: idx = ((ks*8+mf)*32 + lane)*4 + reg, stride 4 per c
            {
                const int reg = a_rb + ((c8 >> 2) << 1);
                const int base = ((ks * 8 + a_mf) * 32 + a_lb + (c8 & 3)) * 4 + reg;
                float h, l;
                h = tf32_rna(av.x); l = tf32_rna(av.x - h);
                sm[F_AHI + base]      = h; sm[F_ALO + base]      = l;
                h = tf32_rna(av.y); l = tf32_rna(av.y - h);
                sm[F_AHI + base + 4]  = h; sm[F_ALO + base + 4]  = l;
                h = tf32_rna(av.z); l = tf32_rna(av.z - h);
                sm[F_AHI + base + 8]  = h; sm[F_ALO + base + 8]  = l;
                h = tf32_rna(av.w); l = tf32_rna(av.w - h);
                sm[F_AHI + base + 12] = h; sm[F_ALO + base + 12] = l;
            }
            // B scatter: idx = ((ks*16+nf)*32 + lane)*2 + reg, lane|=k&3
            {
                const int reg = c8 >> 2;
                const int base = ((ks * 16 + b_nf) * 32 + b_lb + (c8 & 3)) * 2 + reg;
                float h, l;
                h = tf32_rna(bv.x); l = tf32_rna(bv.x - h);
                sm[F_BHI + base]     = h; sm[F_BLO + base]     = l;
                h = tf32_rna(bv.y); l = tf32_rna(bv.y - h);
                sm[F_BHI + base + 2] = h; sm[F_BLO + base + 2] = l;
                h = tf32_rna(bv.z); l = tf32_rna(bv.z - h);
                sm[F_BHI + base + 4] = h; sm[F_BLO + base + 4] = l;
                h = tf32_rna(bv.w); l = tf32_rna(bv.w - h);
                sm[F_BHI + base + 6] = h; sm[F_BLO + base + 6] = l;
            }
        }
        __syncthreads();

        // ---- compute: 4 k-steps ----
#pragma unroll
        for (int ks = 0; ks < 4; ks++) {
            uint32_t ahi[4][4], alo[4][4], bhi[4][2], blo[4][2];
#pragma unroll
            for (int mf = 0; mf < 4; mf++) {
                const int mfg = wm * 4 + mf;
                const int ix = ((ks * 8 + mfg) * 32 + lane) * 4;
                *reinterpret_cast<float4*>(ahi[mf]) =
                    *reinterpret_cast<const float4*>(&sm[F_AHI + ix]);
                *reinterpret_cast<float4*>(alo[mf]) =
                    *reinterpret_cast<const float4*>(&sm[F_ALO + ix]);
            }
#pragma unroll
            for (int nf = 0; nf < 4; nf++) {
                const int nfg = wn * 4 + nf;
                const int ix = ((ks * 16 + nfg) * 32 + lane) * 2;
                *reinterpret_cast<float2*>(bhi[nf]) =
                    *reinterpret_cast<const float2*>(&sm[F_BHI + ix]);
                *reinterpret_cast<float2*>(blo[nf]) =
                    *reinterpret_cast<const float2*>(&sm[F_BLO + ix]);
            }
#pragma unroll
            for (int mf = 0; mf < 4; mf++)
#pragma unroll
                for (int nf = 0; nf < 4; nf++) {
                    mma_tf32(acc[mf][nf], ahi[mf], bhi[nf]);
                    mma_tf32(acc[mf][nf], ahi[mf], blo[nf]);
                    mma_tf32(acc[mf][nf], alo[mf], bhi[nf]);
                }
        }
        __syncthreads();
    }

    // ---- epilogue ----
#pragma unroll
    for (int mf = 0; mf < 4; mf++) {
        const int row0 = bm + wm * 64 + mf * 16 + (lane >> 2);
#pragma unroll
        for (int nf = 0; nf < 4; nf++) {
            const int col0 = bn + wn * 32 + nf * 8 + 2 * (lane & 3);
            const float bb0 = bias[col0];
            const float bb1 = bias[col0 + 1];
            float2 v0, v1;
            v0.x = acc[mf][nf][0] + bb0;
            v0.y = acc[mf][nf][1] + bb1;
            v1.x = acc[mf][nf][2] + bb0;
            v1.y = acc[mf][nf][3] + bb1;
            *reinterpret_cast<float2*>(&g_pre[(size_t)row0 * Hv + col0]) = v0;
            *reinterpret_cast<float2*>(&g_pre[(size_t)(row0 + 8) * Hv + col0]) = v1;
        }
    }
}

// ---------------------------------------------------------------------------
// fast warp argmax over lanes [0, Vv): monotone-uint transform + redux.max +
// ballot + ffs.  Uniform across the warp; first-max tie-break (jnp.argmax).
// ---------------------------------------------------------------------------
__device__ __forceinline__ int argmax17(float v, int lane)
{
    unsigned u = __float_as_uint(v);
    u = (u & 0x80000000u) ? ~u : (u | 0x80000000u);
    if (lane >= Vv) u = 0u;
    unsigned mx = __reduce_max_sync(FULLMASK, u);
    unsigned msk = __ballot_sync(FULLMASK, u == mx);
    return __ffs(msk) - 1;
}

// ---------------------------------------------------------------------------
// Kernel 2: sequential scan (unchanged from R4 best).
// ---------------------------------------------------------------------------
__global__ __launch_bounds__(544) void scan_kernel(
    const float* __restrict__ emb_table,   // [V, E]
    const float* __restrict__ W1,          // [H, D+E]
    const float* __restrict__ W2,          // [V, H]
    const float* __restrict__ b2,          // [V]
    float* __restrict__ out)
{
    __shared__ float sM[Vv][Hv];
    __shared__ float sH[Hv];
    __shared__ float sLogit[20];

    const int b    = blockIdx.x;
    const int tid  = threadIdx.x;
    const int w    = tid >> 5;
    const int lane = tid & 31;

    for (int idx = tid; idx < Vv * Hv; idx += 544) {
        int v = idx / Hv, h = idx - v * Hv;
        float acc = 0.f;
        if (v != 0) {
            const float* er = emb_table + v * Ev;
            const float* wr = W1 + (size_t)h * (Dv + Ev) + Dv;
#pragma unroll 8
            for (int e = 0; e < Ev; e++) acc += er[e] * wr[e];
        }
        sM[v][h] = acc;
    }

    float w2r[16];
#pragma unroll
    for (int k = 0; k < 16; k++) w2r[k] = W2[(size_t)w * Hv + k * 32 + lane];
    const float bias2 = b2[w];
    __syncthreads();

    float* outL = out + OFF_LOGITS;
    float* outP = out + OFF_PREDS;

    const float* preB = g_pre + (size_t)b * Lv * Hv;

    float pcur = (tid < Hv) ? preB[tid] : 0.f;

    for (int t = 0; t < Lv; t++) {
        float pnxt = 0.f;
        if (tid < Hv && t + 1 < Lv) pnxt = preB[(size_t)(t + 1) * Hv + tid];

        int pred;
        if (t == 0) {
            pred = 0;   // PAD
        } else {
            pred = argmax17((lane < Vv) ? sLogit[lane] : 0.f, lane);
            if (tid == 0) outP[(size_t)b * Lv + (t - 1)] = (float)pred;
        }
        if (tid < Hv) sH[tid] = tanhf(pcur + sM[pred][tid]);
        __syncthreads();

        {
            float acc = 0.f;
#pragma unroll
            for (int k = 0; k < 16; k++) acc += sH[k * 32 + lane] * w2r[k];
#pragma unroll
            for (int off = 16; off; off >>= 1)
                acc += __shfl_xor_sync(FULLMASK, acc, off);
            if (lane == 0) {
                float lg = acc + bias2;
                sLogit[w] = lg;
                outL[((size_t)b * Lv + t) * Vv + w] = lg;
            }
        }
        __syncthreads();

        pcur = pnxt;
    }

    if (w == 0) {
        int pred = argmax17((lane < Vv) ? sLogit[lane] : 0.f, lane);
        if (lane == 0) outP[(size_t)b * Lv + (Lv - 1)] = (float)pred;
    }
}

// ---------------------------------------------------------------------------
// Kernel 3: parallel post-pass — log-softmax from saved logits, preds_emb.
// ---------------------------------------------------------------------------
__global__ __launch_bounds__(256) void post_kernel(
    const float* __restrict__ emb_table,
    float* __restrict__ out)
{
    const float* outL = out + OFF_LOGITS;
    const float* outP = out + OFF_PREDS;
    float* outQ  = out + OFF_PROBS;
    float* outEb = out + OFF_EMB;

    const int lane = threadIdx.x & 31;
    const int warps_total = (gridDim.x * blockDim.x) >> 5;
    int gw = (blockIdx.x * blockDim.x + threadIdx.x) >> 5;

    for (int row = gw; row < Bv * Lv; row += warps_total) {
        float v = (lane < Vv) ? outL[(size_t)row * Vv + lane] : -1e30f;
        float m = v;
#pragma unroll
        for (int off = 16; off; off >>= 1)
            m = fmaxf(m, __shfl_xor_sync(FULLMASK, m, off));
        float e = (lane < Vv) ? expf(v - m) : 0.f;
        float s = e;
#pragma unroll
        for (int off = 16; off; off >>= 1)
            s += __shfl_xor_sync(FULLMASK, s, off);
        float lse = m + logf(s);
        if (lane < Vv) outQ[(size_t)row * Vv + lane] = v - lse;

        int pred = (int)outP[row];
        float e0 = (pred != 0) ? emb_table[pred * Ev + lane] : 0.f;
        float e1 = (pred != 0) ? emb_table[pred * Ev + 32 + lane] : 0.f;
        outEb[(size_t)row * Ev + lane]      = e0;
        outEb[(size_t)row * Ev + 32 + lane] = e1;
    }
}

// ---------------------------------------------------------------------------
extern "C" void kernel_launch(void* const* d_in, const int* in_sizes, int n_in,
                              void* d_out, int out_size)
{
    const float* inputs    = (const float*)d_in[0];  // [B, L, D]
    const float* emb_table = (const float*)d_in[1];  // [V, E]
    const float* W1        = (const float*)d_in[2];  // [H, D+E]
    const float* b1        = (const float*)d_in[3];  // [H]
    const float* W2        = (const float*)d_in[4];  // [V, H]
    const float* b2        = (const float*)d_in[5];  // [V]
    float* out = (float*)d_out;

    (void)in_sizes; (void)n_in; (void)out_size;

    cudaFuncSetAttribute(gemm_mma_kernel,
                         cudaFuncAttributeMaxDynamicSharedMemorySize,
                         SM_TOT_BYTES);

    gemm_mma_kernel<<<2048, 256, SM_TOT_BYTES>>>(inputs, W1, b1);

    scan_kernel<<<Bv, 544>>>(emb_table, W1, W2, b2, out);

    post_kernel<<<256, 256>>>(emb_table, out);
}

// round 10
// speedup vs baseline: 2.6476x; 1.2405x over previous
#include <cuda_runtime.h>
#include <cuda_bf16.h>
#include <cstdint>
#include <math.h>

// Problem dims
#define Bv 128
#define Lv 512
#define Dv 512
#define Ev 64
#define Hv 512
#define Vv 17

#define FULLMASK 0xffffffffu

// Output layout (float32 concat of the 4 reference outputs)
#define OFF_LOGITS 0
#define OFF_PREDS  (Bv*Lv*Vv)                 // 1114112
#define OFF_PROBS  (OFF_PREDS + Bv*Lv)        // 1179648
#define OFF_EMB    (OFF_PROBS + Bv*Lv*Vv)     // 2293760

// Scratch: pre[b, t, h] = inputs[b,t,:] @ W1[:, :D]^T + b1   (128 MB)
__device__ float g_pre[(size_t)Bv * Lv * Hv];

// ---------------------------------------------------------------------------
__device__ __forceinline__ float lo_part(float x) {
    float h = __uint_as_float(__float_as_uint(x) & 0xFFFFE000u);
    return x - h;   // exact
}

__device__ __forceinline__ void mma_tf32(
    float* d, const uint32_t* a, const uint32_t* b)
{
    asm volatile(
        "mma.sync.aligned.m16n8k8.row.col.f32.tf32.tf32.f32 "
        "{%0,%1,%2,%3}, {%4,%5,%6,%7}, {%8,%9}, {%0,%1,%2,%3};\n"
        : "+f"(d[0]), "+f"(d[1]), "+f"(d[2]), "+f"(d[3])
        : "r"(a[0]), "r"(a[1]), "r"(a[2]), "r"(a[3]),
          "r"(b[0]), "r"(b[1]));
}

// dynamic smem layout in floats: A | B, 4096 floats each (32KB total)
#define F_A 0
#define F_B 4096
#define SM_TOT_BYTES (8192 * 4)

// ---------------------------------------------------------------------------
// Kernel 1: pre = A @ W1x^T + b1 via mma.sync tf32, 3-term precision split
// with the hi/lo split done IN REGISTERS after the fragment load (raw f32 in
// smem; MMA HW truncates f32->tf32, lo = x - trunc(x)).
// 2048 CTAs x 256 threads, 128x128 tile, BK=32.
// Fragment-major smem layout so each fragment load is one LDS.128 / LDS.64:
//   A: [ks(4)][mf(8)][lane(32)][reg(4)]   (4096 floats)
//   B: [ks(4)][nf(16)][lane(32)][reg(2)]  (4096 floats)
// ---------------------------------------------------------------------------
__global__ __launch_bounds__(256) void gemm_mma_kernel(
    const float* __restrict__ A,      // [B*L, D]
    const float* __restrict__ W,      // [H, D+E]
    const float* __restrict__ bias)   // [H]
{
    extern __shared__ float sm[];

    const int tid  = threadIdx.x;
    const int w    = tid >> 5;
    const int lane = tid & 31;
    const int wm   = w >> 2;          // 0..1  (m offset 64)
    const int wn   = w & 3;           // 0..3  (n offset 32)

    const int bm = (blockIdx.x >> 2) * 128;   // row block in [B*L]
    const int bn = (blockIdx.x & 3) * 128;    // col block in [H]

    // staging mapping: thread t handles row = t>>1, k-cols cgrp..cgrp+15
    const int srow = tid >> 1;
    const int cgrp = (tid & 1) * 16;

    const float* aP = A + (size_t)(bm + srow) * Dv + cgrp;
    const float* wP = W + (size_t)(bn + srow) * (Dv + Ev) + cgrp;

    float acc[4][4][4];
#pragma unroll
    for (int i = 0; i < 4; i++)
#pragma unroll
        for (int j = 0; j < 4; j++)
#pragma unroll
            for (int r = 0; r < 4; r++) acc[i][j][r] = 0.f;

    // A-row scatter base pieces (row fixed per thread)
    const int a_mf  = srow >> 4;
    const int a_r16 = srow & 15;
    const int a_lb  = (a_r16 & 7) << 2;       // lane base (+= c&3)
    const int a_rb  = a_r16 >> 3;             // reg base  (+= 2*(c8>>2))
    // B-row scatter base pieces
    const int b_nf  = srow >> 3;
    const int b_lb  = (srow & 7) << 2;

    for (int ch = 0; ch < 16; ch++) {
        const int k0 = ch * 32;
        // ---- stage: load 16 A + 16 B floats, scatter raw f32 to frag layout
#pragma unroll
        for (int q = 0; q < 4; q++) {
            const int kc = cgrp + q * 4;          // chunk-local k col (mult of 4)
            const int ks = kc >> 3;
            const int c8 = kc & 7;
            float4 av = *reinterpret_cast<const float4*>(aP + k0 + q * 4);
            float4 bv = *reinterpret_cast<const float4*>(wP + k0 + q * 4);

            // A scatter: idx = ((ks*8+mf)*32 + lane)*4 + reg, stride 4 per c
            {
                const int reg = a_rb + ((c8 >> 2) << 1);
                const int base = ((ks * 8 + a_mf) * 32 + a_lb + (c8 & 3)) * 4 + reg;
                sm[F_A + base]      = av.x;
                sm[F_A + base + 4]  = av.y;
                sm[F_A + base + 8]  = av.z;
                sm[F_A + base + 12] = av.w;
            }
            // B scatter: idx = ((ks*16+nf)*32 + lane)*2 + reg, lane += k&3
            {
                const int reg = c8 >> 2;
                const int base = ((ks * 16 + b_nf) * 32 + b_lb + (c8 & 3)) * 2 + reg;
                sm[F_B + base]     = bv.x;
                sm[F_B + base + 2] = bv.y;
                sm[F_B + base + 4] = bv.z;
                sm[F_B + base + 6] = bv.w;
            }
        }
        __syncthreads();

        // ---- compute: 4 k-steps ----
#pragma unroll
        for (int ks = 0; ks < 4; ks++) {
            float    afr[4][4];
            uint32_t alo[4][4];
            float    bfr[4][2];
            uint32_t blo[4][2];
#pragma unroll
            for (int mf = 0; mf < 4; mf++) {
                const int mfg = wm * 4 + mf;
                const int ix = ((ks * 8 + mfg) * 32 + lane) * 4;
                *reinterpret_cast<float4*>(afr[mf]) =
                    *reinterpret_cast<const float4*>(&sm[F_A + ix]);
#pragma unroll
                for (int r = 0; r < 4; r++)
                    alo[mf][r] = __float_as_uint(lo_part(afr[mf][r]));
            }
#pragma unroll
            for (int nf = 0; nf < 4; nf++) {
                const int nfg = wn * 4 + nf;
                const int ix = ((ks * 16 + nfg) * 32 + lane) * 2;
                *reinterpret_cast<float2*>(bfr[nf]) =
                    *reinterpret_cast<const float2*>(&sm[F_B + ix]);
#pragma unroll
                for (int r = 0; r < 2; r++)
                    blo[nf][r] = __float_as_uint(lo_part(bfr[nf][r]));
            }
#pragma unroll
            for (int mf = 0; mf < 4; mf++)
#pragma unroll
                for (int nf = 0; nf < 4; nf++) {
                    const uint32_t* ahi =
                        reinterpret_cast<const uint32_t*>(afr[mf]);
                    const uint32_t* bhi =
                        reinterpret_cast<const uint32_t*>(bfr[nf]);
                    mma_tf32(acc[mf][nf], ahi, bhi);
                    mma_tf32(acc[mf][nf], ahi, blo[nf]);
                    mma_tf32(acc[mf][nf], alo[mf], bhi);
                }
        }
        __syncthreads();
    }

    // ---- epilogue ----
#pragma unroll
    for (int mf = 0; mf < 4; mf++) {
        const int row0 = bm + wm * 64 + mf * 16 + (lane >> 2);
#pragma unroll
        for (int nf = 0; nf < 4; nf++) {
            const int col0 = bn + wn * 32 + nf * 8 + 2 * (lane & 3);
            const float bb0 = bias[col0];
            const float bb1 = bias[col0 + 1];
            float2 v0, v1;
            v0.x = acc[mf][nf][0] + bb0;
            v0.y = acc[mf][nf][1] + bb1;
            v1.x = acc[mf][nf][2] + bb0;
            v1.y = acc[mf][nf][3] + bb1;
            *reinterpret_cast<float2*>(&g_pre[(size_t)row0 * Hv + col0]) = v0;
            *reinterpret_cast<float2*>(&g_pre[(size_t)(row0 + 8) * Hv + col0]) = v1;
        }
    }
}

// ---------------------------------------------------------------------------
// fast warp argmax over lanes [0, Vv): monotone-uint transform + redux.max +
// ballot + ffs.  Uniform across the warp; first-max tie-break (jnp.argmax).
// ---------------------------------------------------------------------------
__device__ __forceinline__ int argmax17(float v, int lane)
{
    unsigned u = __float_as_uint(v);
    u = (u & 0x80000000u) ? ~u : (u | 0x80000000u);
    if (lane >= Vv) u = 0u;
    unsigned mx = __reduce_max_sync(FULLMASK, u);
    unsigned msk = __ballot_sync(FULLMASK, u == mx);
    return __ffs(msk) - 1;
}

// ---------------------------------------------------------------------------
// Kernel 2: sequential scan (unchanged from R4 best).
// ---------------------------------------------------------------------------
__global__ __launch_bounds__(544) void scan_kernel(
    const float* __restrict__ emb_table,   // [V, E]
    const float* __restrict__ W1,          // [H, D+E]
    const float* __restrict__ W2,          // [V, H]
    const float* __restrict__ b2,          // [V]
    float* __restrict__ out)
{
    __shared__ float sM[Vv][Hv];
    __shared__ float sH[Hv];
    __shared__ float sLogit[20];

    const int b    = blockIdx.x;
    const int tid  = threadIdx.x;
    const int w    = tid >> 5;
    const int lane = tid & 31;

    for (int idx = tid; idx < Vv * Hv; idx += 544) {
        int v = idx / Hv, h = idx - v * Hv;
        float acc = 0.f;
        if (v != 0) {
            const float* er = emb_table + v * Ev;
            const float* wr = W1 + (size_t)h * (Dv + Ev) + Dv;
#pragma unroll 8
            for (int e = 0; e < Ev; e++) acc += er[e] * wr[e];
        }
        sM[v][h] = acc;
    }

    float w2r[16];
#pragma unroll
    for (int k = 0; k < 16; k++) w2r[k] = W2[(size_t)w * Hv + k * 32 + lane];
    const float bias2 = b2[w];
    __syncthreads();

    float* outL = out + OFF_LOGITS;
    float* outP = out + OFF_PREDS;

    const float* preB = g_pre + (size_t)b * Lv * Hv;

    float pcur = (tid < Hv) ? preB[tid] : 0.f;

    for (int t = 0; t < Lv; t++) {
        float pnxt = 0.f;
        if (tid < Hv && t + 1 < Lv) pnxt = preB[(size_t)(t + 1) * Hv + tid];

        int pred;
        if (t == 0) {
            pred = 0;   // PAD
        } else {
            pred = argmax17((lane < Vv) ? sLogit[lane] : 0.f, lane);
            if (tid == 0) outP[(size_t)b * Lv + (t - 1)] = (float)pred;
        }
        if (tid < Hv) sH[tid] = tanhf(pcur + sM[pred][tid]);
        __syncthreads();

        {
            float acc = 0.f;
#pragma unroll
            for (int k = 0; k < 16; k++) acc += sH[k * 32 + lane] * w2r[k];
#pragma unroll
            for (int off = 16; off; off >>= 1)
                acc += __shfl_xor_sync(FULLMASK, acc, off);
            if (lane == 0) {
                float lg = acc + bias2;
                sLogit[w] = lg;
                outL[((size_t)b * Lv + t) * Vv + w] = lg;
            }
        }
        __syncthreads();

        pcur = pnxt;
    }

    if (w == 0) {
        int pred = argmax17((lane < Vv) ? sLogit[lane] : 0.f, lane);
        if (lane == 0) outP[(size_t)b * Lv + (Lv - 1)] = (float)pred;
    }
}

// ---------------------------------------------------------------------------
// Kernel 3: parallel post-pass — log-softmax from saved logits, preds_emb.
// ---------------------------------------------------------------------------
__global__ __launch_bounds__(256) void post_kernel(
    const float* __restrict__ emb_table,
    float* __restrict__ out)
{
    const float* outL = out + OFF_LOGITS;
    const float* outP = out + OFF_PREDS;
    float* outQ  = out + OFF_PROBS;
    float* outEb = out + OFF_EMB;

    const int lane = threadIdx.x & 31;
    const int warps_total = (gridDim.x * blockDim.x) >> 5;
    int gw = (blockIdx.x * blockDim.x + threadIdx.x) >> 5;

    for (int row = gw; row < Bv * Lv; row += warps_total) {
        float v = (lane < Vv) ? outL[(size_t)row * Vv + lane] : -1e30f;
        float m = v;
#pragma unroll
        for (int off = 16; off; off >>= 1)
            m = fmaxf(m, __shfl_xor_sync(FULLMASK, m, off));
        float e = (lane < Vv) ? expf(v - m) : 0.f;
        float s = e;
#pragma unroll
        for (int off = 16; off; off >>= 1)
            s += __shfl_xor_sync(FULLMASK, s, off);
        float lse = m + logf(s);
        if (lane < Vv) outQ[(size_t)row * Vv + lane] = v - lse;

        int pred = (int)outP[row];
        float e0 = (pred != 0) ? emb_table[pred * Ev + lane] : 0.f;
        float e1 = (pred != 0) ? emb_table[pred * Ev + 32 + lane] : 0.f;
        outEb[(size_t)row * Ev + lane]      = e0;
        outEb[(size_t)row * Ev + 32 + lane] = e1;
    }
}

// ---------------------------------------------------------------------------
extern "C" void kernel_launch(void* const* d_in, const int* in_sizes, int n_in,
                              void* d_out, int out_size)
{
    const float* inputs    = (const float*)d_in[0];  // [B, L, D]
    const float* emb_table = (const float*)d_in[1];  // [V, E]
    const float* W1        = (const float*)d_in[2];  // [H, D+E]
    const float* b1        = (const float*)d_in[3];  // [H]
    const float* W2        = (const float*)d_in[4];  // [V, H]
    const float* b2        = (const float*)d_in[5];  // [V]
    float* out = (float*)d_out;

    (void)in_sizes; (void)n_in; (void)out_size;

    cudaFuncSetAttribute(gemm_mma_kernel,
                         cudaFuncAttributeMaxDynamicSharedMemorySize,
                         SM_TOT_BYTES);

    gemm_mma_kernel<<<2048, 256, SM_TOT_BYTES>>>(inputs, W1, b1);

    scan_kernel<<<Bv, 544>>>(emb_table, W1, W2, b2, out);

    post_kernel<<<256, 256>>>(emb_table, out);
}